// round 12
// baseline (speedup 1.0000x reference)
#include <cuda_runtime.h>
#include <cuda_fp16.h>
#include <cstdint>
#include <math.h>

typedef unsigned int u32;

#define Bb 2
#define Ll 2048
#define Mm 2048
#define Dd 1024
#define Hh 16
#define DHh 64
#define FFf 4096
#define WINW 64
#define RB (Bb*Ll)      // 4096 rows
#define SEG (RB*Dd)     // 4194304

#define M1 (1024*1024)

// fp32 scratch: btmp, bx1, bx2
__device__ float g_f32[(size_t)SEG*3];
// fp16 scratch
__device__ __half g_f16[(size_t)64*M1];

#define CP16(dst, src) asm volatile("cp.async.cg.shared.global [%0], [%1], 16;" :: "r"(dst), "l"(src))
#define CPCOMMIT()     asm volatile("cp.async.commit_group;")

#define MBARRIER_INIT(mbar, cnt) \
    asm volatile("mbarrier.init.shared.b64 [%0], %1;" :: "r"((u32)(mbar)), "r"((u32)(cnt)) : "memory")
#define MBARRIER_EXPECT_TX(mbar, bytes) \
    asm volatile("mbarrier.arrive.expect_tx.shared.b64 _, [%0], %1;" :: "r"((u32)(mbar)), "r"((u32)(bytes)) : "memory")
#define MBARRIER_WAIT_ACQ(mbar, par) do { \
    u32 _m = (u32)(mbar); u32 _p = (u32)(par); u32 _done; \
    asm volatile("{\n\t.reg .pred p;\n\t" \
        "mbarrier.try_wait.parity.acquire.cta.shared::cta.b64 p, [%1], %2;\n\t" \
        "selp.b32 %0, 1, 0, p;\n\t}" : "=r"(_done) : "r"(_m), "r"(_p) : "memory"); \
    if (!_done) { \
        asm volatile("{\n\t.reg .pred P1;\n\t" \
            "WAIT_LOOP_%=:\n\t" \
            "mbarrier.try_wait.parity.acquire.cta.shared::cta.b64 P1, [%0], %1, 0x989680;\n\t" \
            "@P1 bra.uni WAIT_DONE_%=;\n\tbra.uni WAIT_LOOP_%=;\n\tWAIT_DONE_%=:\n\t}" \
            :: "r"(_m), "r"(_p) : "memory"); \
    } \
} while (0)

#define BULK64(dst, src, mb) \
    asm volatile("cp.async.bulk.shared::cluster.global.mbarrier::complete_tx::bytes [%0], [%1], 64, [%2];" \
        :: "r"((u32)(dst)), "l"(src), "r"((u32)(mb)) : "memory")
#define BULK256(dst, src, mb) \
    asm volatile("cp.async.bulk.shared::cluster.global.mbarrier::complete_tx::bytes [%0], [%1], 256, [%2];" \
        :: "r"((u32)(dst)), "l"(src), "r"((u32)(mb)) : "memory")

// ---------------------------------------------------------------------------
// Batched fp32 -> fp16 conversion (12 tensors in one launch).
// ---------------------------------------------------------------------------
struct CvtJob { const float* src; __half* dst; int n; };
struct CvtArgs { CvtJob job[12]; };

__global__ __launch_bounds__(256) void cvt_kernel(CvtArgs a) {
    CvtJob j = a.job[blockIdx.y];
    int stride = gridDim.x * 256 * 8;
    for (int base = (blockIdx.x * 256 + threadIdx.x) * 8; base < j.n; base += stride) {
        float4 f0 = *(const float4*)(j.src + base);
        float4 f1 = *(const float4*)(j.src + base + 4);
        __half2 h0 = __floats2half2_rn(f0.x, f0.y);
        __half2 h1 = __floats2half2_rn(f0.z, f0.w);
        __half2 h2 = __floats2half2_rn(f1.x, f1.y);
        __half2 h3 = __floats2half2_rn(f1.z, f1.w);
        uint4 o;
        o.x = *(u32*)&h0; o.y = *(u32*)&h1; o.z = *(u32*)&h2; o.w = *(u32*)&h3;
        *(uint4*)(j.dst + base) = o;
    }
}

// ---------------------------------------------------------------------------
// fp16 tensor-core GEMM with cp.async.bulk (TMA bulk copy) loads.
// 3-stage ring, mbarrier complete_tx per stage, 160 bulk ops/stage instead of
// 1024 LDGSTS. Unswizzled smem with padded pitches (A 80B, B 272B) chosen for
// conflict-free ldmatrix. Compute loop identical to the R10-passing kernel.
// ---------------------------------------------------------------------------
#define NSTAGE 3
#define A_PITCH 80
#define B_PITCH 272
#define B_OFF (128 * A_PITCH)            // 10240
#define STG_STRIDE 19456                 // >= 10240 + 32*272 = 18944, 1KB aligned
#define HG_SMEM (1024 + NSTAGE * STG_STRIDE)   // 59392

template<bool GELU>
__global__ __launch_bounds__(256, 2) void hgemm16_kernel(
    const __half* __restrict__ A, const __half* __restrict__ Wm,
    const float* __restrict__ bias, float* __restrict__ C32,
    __half* __restrict__ C16, int K, int N)
{
    extern __shared__ __align__(16) unsigned char dsm[];
    const u32 base = (u32)__cvta_generic_to_shared(dsm);
    const u32 stb = base + 1024;

    const int tid = threadIdx.x;
    const int lane = tid & 31, wid = tid >> 5;
    const int warp_m = wid >> 2, warp_n = wid & 3;
    const int row0 = blockIdx.y * 128, col0 = blockIdx.x * 128;
    const int ntiles = K >> 5;

    if (tid == 0) {
        #pragma unroll
        for (int s = 0; s < NSTAGE; s++) MBARRIER_INIT(base + s * 8, 1);
    }
    __syncthreads();

    // warp-0 stage issue: 128 A-row bulks (64B) + 32 B-row bulks (256B)
    auto issue = [&](int t, int s) {
        u32 mb = base + s * 8;
        u32 st = stb + s * STG_STRIDE;
        int k0 = t << 5;
        if (lane == 0) MBARRIER_EXPECT_TX(mb, 16384u);
        __syncwarp();
        #pragma unroll
        for (int i = 0; i < 4; i++) {
            int r = lane + i * 32;
            BULK64(st + r * A_PITCH, A + (size_t)(row0 + r) * K + k0, mb);
        }
        BULK256(st + B_OFF + lane * B_PITCH, Wm + (size_t)(k0 + lane) * N + col0, mb);
    };

    if (wid == 0) { issue(0, 0); if (ntiles > 1) issue(1, 1); }

    float acc[4][4][4];
    #pragma unroll
    for (int i = 0; i < 4; i++)
        #pragma unroll
        for (int j = 0; j < 4; j++)
            #pragma unroll
            for (int q = 0; q < 4; q++) acc[i][j][q] = 0.f;

    int s = 0, ph = 0;
    for (int t = 0; t < ntiles; t++) {
        MBARRIER_WAIT_ACQ(base + s * 8, ph);
        __syncthreads();   // all warps done with stage (t+2)%3's previous use

        if (wid == 0 && t + 2 < ntiles) {
            int s2 = s + 2; if (s2 >= NSTAGE) s2 -= NSTAGE;
            issue(t + 2, s2);
        }

        const u32 sA = stb + s * STG_STRIDE;
        const u32 sB = sA + B_OFF;

        #pragma unroll
        for (int ks = 0; ks < 2; ks++) {
            u32 af[4][4];
            #pragma unroll
            for (int mt = 0; mt < 4; mt++) {
                int rr = warp_m * 64 + mt * 16 + ((lane >> 3) & 1) * 8 + (lane & 7);
                int cc = ks * 2 + (lane >> 4);
                u32 aaddr = sA + rr * A_PITCH + (cc << 4);
                asm volatile(
                    "ldmatrix.sync.aligned.m8n8.x4.shared.b16 {%0,%1,%2,%3}, [%4];"
                    : "=r"(af[mt][0]), "=r"(af[mt][1]), "=r"(af[mt][2]), "=r"(af[mt][3])
                    : "r"(aaddr));
            }
            #pragma unroll
            for (int nt = 0; nt < 4; nt++) {
                int rr = ks * 16 + (lane & 15);
                int cc = warp_n * 4 + nt;
                u32 baddr = sB + rr * B_PITCH + (cc << 4);
                u32 bf0, bf1;
                asm volatile(
                    "ldmatrix.sync.aligned.m8n8.x2.trans.shared.b16 {%0,%1}, [%2];"
                    : "=r"(bf0), "=r"(bf1) : "r"(baddr));
                #pragma unroll
                for (int mt = 0; mt < 4; mt++) {
                    asm volatile(
                        "mma.sync.aligned.m16n8k16.row.col.f32.f16.f16.f32 "
                        "{%0,%1,%2,%3}, {%4,%5,%6,%7}, {%8,%9}, {%0,%1,%2,%3};"
                        : "+f"(acc[mt][nt][0]), "+f"(acc[mt][nt][1]),
                          "+f"(acc[mt][nt][2]), "+f"(acc[mt][nt][3])
                        : "r"(af[mt][0]), "r"(af[mt][1]), "r"(af[mt][2]), "r"(af[mt][3]),
                          "r"(bf0), "r"(bf1));
                }
            }
        }

        if (++s == NSTAGE) { s = 0; ph ^= 1; }
    }

    const int g = lane >> 2, tl = lane & 3;
    #pragma unroll
    for (int nt = 0; nt < 4; nt++) {
        int col = col0 + warp_n * 32 + nt * 8 + 2 * tl;
        float2 bb = *(const float2*)&bias[col];
        #pragma unroll
        for (int mt = 0; mt < 4; mt++) {
            int rlo = row0 + warp_m * 64 + mt * 16 + g;
            float2 olo, ohi;
            olo.x = acc[mt][nt][0] + bb.x;
            olo.y = acc[mt][nt][1] + bb.y;
            ohi.x = acc[mt][nt][2] + bb.x;
            ohi.y = acc[mt][nt][3] + bb.y;
            if (GELU) {
                olo.x = 0.5f * olo.x * (1.0f + erff(olo.x * 0.70710678118654752f));
                olo.y = 0.5f * olo.y * (1.0f + erff(olo.y * 0.70710678118654752f));
                ohi.x = 0.5f * ohi.x * (1.0f + erff(ohi.x * 0.70710678118654752f));
                ohi.y = 0.5f * ohi.y * (1.0f + erff(ohi.y * 0.70710678118654752f));
            }
            if (C32) {
                *(float2*)&C32[(size_t)rlo * N + col] = olo;
                *(float2*)&C32[(size_t)(rlo + 8) * N + col] = ohi;
            }
            if (C16) {
                __half2 hlo = __floats2half2_rn(olo.x, olo.y);
                __half2 hhi = __floats2half2_rn(ohi.x, ohi.y);
                *(__half2*)&C16[(size_t)rlo * N + col] = hlo;
                *(__half2*)&C16[(size_t)(rlo + 8) * N + col] = hhi;
            }
        }
    }
}

// ---------------------------------------------------------------------------
// MMA flash attention (unchanged — passing since R5).
// ---------------------------------------------------------------------------
template<bool WINDOWED>
__global__ __launch_bounds__(128) void attn_mma_kernel(
    const __half* __restrict__ q, const __half* __restrict__ k,
    const __half* __restrict__ v, __half* __restrict__ out, int Lk)
{
    __shared__ __align__(16) __half Q_s[64 * 64];
    __shared__ __align__(16) __half K_s[2][64 * 64];
    __shared__ __align__(16) __half V_s[2][64 * 64];

    const int tid = threadIdx.x;
    const int lane = tid & 31, wid = tid >> 5;
    const int b = blockIdx.y >> 4, h = blockIdx.y & 15;
    const int q0 = blockIdx.x * 64;

    const __half* qb = q + (size_t)(b * Ll + q0) * Dd + h * DHh;
    const __half* kb = k + (size_t)b * Lk * Dd + h * DHh;
    const __half* vb = v + (size_t)b * Lk * Dd + h * DHh;

    const u32 sQ  = (u32)__cvta_generic_to_shared(Q_s);
    const u32 sK0 = (u32)__cvta_generic_to_shared(K_s);
    const u32 sV0 = (u32)__cvta_generic_to_shared(V_s);

    const float slope = WINDOWED ? exp2f(-0.5f * (float)(h + 1)) : 0.0f;

    int t0 = 0, t1 = Lk / 64 - 1;
    if (WINDOWED) { t0 = (q0 >> 6) - 1; if (t0 < 0) t0 = 0; t1 = q0 >> 6; }

    const int lr = tid >> 1, lc0 = (tid & 1) * 4;

    #pragma unroll
    for (int c = 0; c < 4; c++) {
        int cc = lc0 + c;
        CP16(sQ + lr * 128 + ((cc ^ (lr & 7)) << 4), qb + (size_t)lr * Dd + cc * 8);
    }
    CPCOMMIT();
    {
        const __half* kr = kb + (size_t)(t0 * 64 + lr) * Dd;
        const __half* vr = vb + (size_t)(t0 * 64 + lr) * Dd;
        #pragma unroll
        for (int c = 0; c < 4; c++) {
            int cc = lc0 + c;
            u32 doff = lr * 128 + ((cc ^ (lr & 7)) << 4);
            CP16(sK0 + doff, kr + cc * 8);
            CP16(sV0 + doff, vr + cc * 8);
        }
        CPCOMMIT();
    }
    asm volatile("cp.async.wait_group 0;");
    __syncthreads();

    u32 qf[4][4];
    #pragma unroll
    for (int ks = 0; ks < 4; ks++) {
        int rr = wid * 16 + ((lane >> 3) & 1) * 8 + (lane & 7);
        int cc = ks * 2 + (lane >> 4);
        u32 addr = sQ + rr * 128 + ((cc ^ (rr & 7)) << 4);
        asm volatile(
            "ldmatrix.sync.aligned.m8n8.x4.shared.b16 {%0,%1,%2,%3}, [%4];"
            : "=r"(qf[ks][0]), "=r"(qf[ks][1]), "=r"(qf[ks][2]), "=r"(qf[ks][3])
            : "r"(addr));
    }

    float m0 = -3.4e38f, m1 = -3.4e38f, l0 = 0.f, l1 = 0.f;
    float oacc[8][4];
    #pragma unroll
    for (int nt = 0; nt < 8; nt++)
        #pragma unroll
        for (int e = 0; e < 4; e++) oacc[nt][e] = 0.f;

    const int qr = lane >> 2;
    const int qc2 = (lane & 3) << 1;

    for (int t = t0; t <= t1; t++) {
        int buf = (t - t0) & 1;
        if (t < t1) {
            u32 off = (buf ^ 1) * 8192;
            const __half* kr = kb + (size_t)((t + 1) * 64 + lr) * Dd;
            const __half* vr = vb + (size_t)((t + 1) * 64 + lr) * Dd;
            #pragma unroll
            for (int c = 0; c < 4; c++) {
                int cc = lc0 + c;
                u32 doff = lr * 128 + ((cc ^ (lr & 7)) << 4);
                CP16(sK0 + off + doff, kr + cc * 8);
                CP16(sV0 + off + doff, vr + cc * 8);
            }
            CPCOMMIT();
            asm volatile("cp.async.wait_group 1;");
        } else {
            asm volatile("cp.async.wait_group 0;");
        }
        __syncthreads();

        const u32 sK = sK0 + buf * 8192;
        const u32 sV = sV0 + buf * 8192;

        float sacc[8][4];
        #pragma unroll
        for (int nt = 0; nt < 8; nt++) {
            sacc[nt][0] = sacc[nt][1] = sacc[nt][2] = sacc[nt][3] = 0.f;
            #pragma unroll
            for (int ks = 0; ks < 4; ks++) {
                int krow = nt * 8 + (lane & 7);
                int cc = ks * 2 + ((lane >> 3) & 1);
                u32 addr = sK + krow * 128 + ((cc ^ (krow & 7)) << 4);
                u32 bf0, bf1;
                asm volatile(
                    "ldmatrix.sync.aligned.m8n8.x2.shared.b16 {%0,%1}, [%2];"
                    : "=r"(bf0), "=r"(bf1) : "r"(addr));
                asm volatile(
                    "mma.sync.aligned.m16n8k16.row.col.f32.f16.f16.f32 "
                    "{%0,%1,%2,%3}, {%4,%5,%6,%7}, {%8,%9}, {%0,%1,%2,%3};"
                    : "+f"(sacc[nt][0]), "+f"(sacc[nt][1]),
                      "+f"(sacc[nt][2]), "+f"(sacc[nt][3])
                    : "r"(qf[ks][0]), "r"(qf[ks][1]), "r"(qf[ks][2]), "r"(qf[ks][3]),
                      "r"(bf0), "r"(bf1));
            }
        }

        float mt0 = -3.4e38f, mt1 = -3.4e38f;
        #pragma unroll
        for (int nt = 0; nt < 8; nt++) {
            #pragma unroll
            for (int e = 0; e < 4; e++) {
                float s = sacc[nt][e] * 0.125f;
                if (WINDOWED) {
                    int i = q0 + wid * 16 + qr + ((e >> 1) << 3);
                    int j = t * 64 + nt * 8 + qc2 + (e & 1);
                    s += slope * (float)(j - i);
                    if (j > i || (i - j) >= WINW) s = -3.4e38f;
                }
                sacc[nt][e] = s;
                if (e < 2) mt0 = fmaxf(mt0, s); else mt1 = fmaxf(mt1, s);
            }
        }
        mt0 = fmaxf(mt0, __shfl_xor_sync(0xffffffffu, mt0, 1));
        mt0 = fmaxf(mt0, __shfl_xor_sync(0xffffffffu, mt0, 2));
        mt1 = fmaxf(mt1, __shfl_xor_sync(0xffffffffu, mt1, 1));
        mt1 = fmaxf(mt1, __shfl_xor_sync(0xffffffffu, mt1, 2));

        float mn0 = fmaxf(m0, mt0), mn1 = fmaxf(m1, mt1);
        bool dead0 = mn0 < -1e37f, dead1 = mn1 < -1e37f;
        float corr0 = dead0 ? 1.f : __expf(m0 - mn0);
        float corr1 = dead1 ? 1.f : __expf(m1 - mn1);

        float ls0 = 0.f, ls1 = 0.f;
        #pragma unroll
        for (int nt = 0; nt < 8; nt++) {
            float p0 = dead0 ? 0.f : __expf(sacc[nt][0] - mn0);
            float p1 = dead0 ? 0.f : __expf(sacc[nt][1] - mn0);
            float p2 = dead1 ? 0.f : __expf(sacc[nt][2] - mn1);
            float p3 = dead1 ? 0.f : __expf(sacc[nt][3] - mn1);
            sacc[nt][0] = p0; sacc[nt][1] = p1; sacc[nt][2] = p2; sacc[nt][3] = p3;
            ls0 += p0 + p1; ls1 += p2 + p3;
        }
        ls0 += __shfl_xor_sync(0xffffffffu, ls0, 1);
        ls0 += __shfl_xor_sync(0xffffffffu, ls0, 2);
        ls1 += __shfl_xor_sync(0xffffffffu, ls1, 1);
        ls1 += __shfl_xor_sync(0xffffffffu, ls1, 2);

        l0 = l0 * corr0 + ls0;
        l1 = l1 * corr1 + ls1;
        m0 = mn0; m1 = mn1;

        #pragma unroll
        for (int nt = 0; nt < 8; nt++) {
            oacc[nt][0] *= corr0; oacc[nt][1] *= corr0;
            oacc[nt][2] *= corr1; oacc[nt][3] *= corr1;
        }

        #pragma unroll
        for (int ks = 0; ks < 4; ks++) {
            __half2 ph0 = __floats2half2_rn(sacc[2*ks][0], sacc[2*ks][1]);
            __half2 ph1 = __floats2half2_rn(sacc[2*ks][2], sacc[2*ks][3]);
            __half2 ph2 = __floats2half2_rn(sacc[2*ks+1][0], sacc[2*ks+1][1]);
            __half2 ph3 = __floats2half2_rn(sacc[2*ks+1][2], sacc[2*ks+1][3]);
            u32 pa0 = *(u32*)&ph0, pa1 = *(u32*)&ph1;
            u32 pa2 = *(u32*)&ph2, pa3 = *(u32*)&ph3;
            #pragma unroll
            for (int nt = 0; nt < 8; nt++) {
                int vrow = ks * 16 + (lane & 15);
                u32 addr = sV + vrow * 128 + ((nt ^ (vrow & 7)) << 4);
                u32 vf0, vf1;
                asm volatile(
                    "ldmatrix.sync.aligned.m8n8.x2.trans.shared.b16 {%0,%1}, [%2];"
                    : "=r"(vf0), "=r"(vf1) : "r"(addr));
                asm volatile(
                    "mma.sync.aligned.m16n8k16.row.col.f32.f16.f16.f32 "
                    "{%0,%1,%2,%3}, {%4,%5,%6,%7}, {%8,%9}, {%0,%1,%2,%3};"
                    : "+f"(oacc[nt][0]), "+f"(oacc[nt][1]),
                      "+f"(oacc[nt][2]), "+f"(oacc[nt][3])
                    : "r"(pa0), "r"(pa1), "r"(pa2), "r"(pa3),
                      "r"(vf0), "r"(vf1));
            }
        }
        __syncthreads();
    }

    float inv0 = 1.0f / l0, inv1 = 1.0f / l1;
    int row_lo = q0 + wid * 16 + qr;
    __half* ob = out + (size_t)(b * Ll) * Dd + h * DHh;
    #pragma unroll
    for (int nt = 0; nt < 8; nt++) {
        __half2 h0 = __floats2half2_rn(oacc[nt][0] * inv0, oacc[nt][1] * inv0);
        __half2 h1 = __floats2half2_rn(oacc[nt][2] * inv1, oacc[nt][3] * inv1);
        *(__half2*)(ob + (size_t)row_lo * Dd + nt * 8 + qc2) = h0;
        *(__half2*)(ob + (size_t)(row_lo + 8) * Dd + nt * 8 + qc2) = h1;
    }
}

// ---------------------------------------------------------------------------
// out = LayerNorm(a + bres) * g + be. Optional fp16 mirror.
// ---------------------------------------------------------------------------
__global__ __launch_bounds__(256) void add_ln_kernel(
    const float* __restrict__ a, const float* __restrict__ bres,
    const float* __restrict__ g, const float* __restrict__ be,
    float* __restrict__ out, __half* __restrict__ out16)
{
    const int row = blockIdx.x;
    const int tid = threadIdx.x;
    const int d4 = tid << 2;

    float4 va = *(const float4*)(a + (size_t)row * Dd + d4);
    float4 vb = *(const float4*)(bres + (size_t)row * Dd + d4);
    float x0 = va.x + vb.x, x1 = va.y + vb.y, x2 = va.z + vb.z, x3 = va.w + vb.w;

    float s = x0 + x1 + x2 + x3;
    float ss = x0 * x0 + x1 * x1 + x2 * x2 + x3 * x3;

    #pragma unroll
    for (int off = 16; off >= 1; off >>= 1) {
        s  += __shfl_down_sync(0xffffffffu, s,  off);
        ss += __shfl_down_sync(0xffffffffu, ss, off);
    }
    __shared__ float rs[8], rss[8];
    __shared__ float s_mu, s_rstd;
    if ((tid & 31) == 0) { rs[tid >> 5] = s; rss[tid >> 5] = ss; }
    __syncthreads();
    if (tid == 0) {
        float S = 0.f, SS = 0.f;
        #pragma unroll
        for (int w = 0; w < 8; w++) { S += rs[w]; SS += rss[w]; }
        float mu = S * (1.0f / Dd);
        float var = SS * (1.0f / Dd) - mu * mu;
        s_mu = mu;
        s_rstd = rsqrtf(var + 1e-5f);
    }
    __syncthreads();
    float mu = s_mu, rstd = s_rstd;

    float4 gg = *(const float4*)(g + d4);
    float4 bb = *(const float4*)(be + d4);
    float4 o;
    o.x = (x0 - mu) * rstd * gg.x + bb.x;
    o.y = (x1 - mu) * rstd * gg.y + bb.y;
    o.z = (x2 - mu) * rstd * gg.z + bb.z;
    o.w = (x3 - mu) * rstd * gg.w + bb.w;
    *(float4*)(out + (size_t)row * Dd + d4) = o;
    if (out16) {
        __half2 h0 = __floats2half2_rn(o.x, o.y);
        __half2 h1 = __floats2half2_rn(o.z, o.w);
        uint2 ho; ho.x = *(u32*)&h0; ho.y = *(u32*)&h1;
        *(uint2*)(out16 + (size_t)row * Dd + d4) = ho;
    }
}

// ---------------------------------------------------------------------------
extern "C" void kernel_launch(void* const* d_in, const int* in_sizes, int n_in,
                              void* d_out, int out_size)
{
    const float* x   = (const float*)d_in[0];
    const float* mem = (const float*)d_in[1];

    const float *swq, *sbq, *swk, *sbk, *swv, *sbv, *swo, *sbo;
    const float *cwq, *cbq, *cwk, *cbk, *cwv, *cbv, *cwo, *cbo;
    const float *w1, *b1, *w2, *b2, *g1, *be1, *g2, *be2, *g3, *be3;

    if (in_sizes[3] == Dd) {
        swq=(const float*)d_in[2];  sbq=(const float*)d_in[3];
        swk=(const float*)d_in[4];  sbk=(const float*)d_in[5];
        swv=(const float*)d_in[6];  sbv=(const float*)d_in[7];
        swo=(const float*)d_in[8];  sbo=(const float*)d_in[9];
        cwq=(const float*)d_in[10]; cbq=(const float*)d_in[11];
        cwk=(const float*)d_in[12]; cbk=(const float*)d_in[13];
        cwv=(const float*)d_in[14]; cbv=(const float*)d_in[15];
        cwo=(const float*)d_in[16]; cbo=(const float*)d_in[17];
        w1=(const float*)d_in[18];  b1=(const float*)d_in[19];
        w2=(const float*)d_in[20];  b2=(const float*)d_in[21];
        g1=(const float*)d_in[22];  be1=(const float*)d_in[23];
        g2=(const float*)d_in[24];  be2=(const float*)d_in[25];
        g3=(const float*)d_in[26];  be3=(const float*)d_in[27];
    } else {
        swq=(const float*)d_in[2];  swk=(const float*)d_in[3];
        swv=(const float*)d_in[4];  swo=(const float*)d_in[5];
        sbq=(const float*)d_in[6];  sbk=(const float*)d_in[7];
        sbv=(const float*)d_in[8];  sbo=(const float*)d_in[9];
        cwq=(const float*)d_in[10]; cwk=(const float*)d_in[11];
        cwv=(const float*)d_in[12]; cwo=(const float*)d_in[13];
        cbq=(const float*)d_in[14]; cbk=(const float*)d_in[15];
        cbv=(const float*)d_in[16]; cbo=(const float*)d_in[17];
        w1=(const float*)d_in[18];  b1=(const float*)d_in[19];
        w2=(const float*)d_in[20];  b2=(const float*)d_in[21];
        g1=(const float*)d_in[22];  g2=(const float*)d_in[23];
        g3=(const float*)d_in[24];
        be1=(const float*)d_in[25]; be2=(const float*)d_in[26];
        be3=(const float*)d_in[27];
    }

    float* s32 = nullptr;
    cudaGetSymbolAddress((void**)&s32, g_f32);
    __half* s16 = nullptr;
    cudaGetSymbolAddress((void**)&s16, g_f16);

    float* btmp = s32;
    float* bx1  = s32 + (size_t)SEG;
    float* bx2  = s32 + (size_t)SEG * 2;

    __half* x16    = s16;
    __half* mem16  = s16 + (size_t)4*M1;
    __half* wq16   = s16 + (size_t)8*M1;
    __half* wk16   = s16 + (size_t)9*M1;
    __half* wv16   = s16 + (size_t)10*M1;
    __half* wo16   = s16 + (size_t)11*M1;
    __half* cq16   = s16 + (size_t)12*M1;
    __half* ck16   = s16 + (size_t)13*M1;
    __half* cv16   = s16 + (size_t)14*M1;
    __half* co16   = s16 + (size_t)15*M1;
    __half* w1_16  = s16 + (size_t)16*M1;
    __half* w2_16  = s16 + (size_t)20*M1;
    __half* bq16   = s16 + (size_t)24*M1;
    __half* bk16   = s16 + (size_t)28*M1;
    __half* bv16   = s16 + (size_t)32*M1;
    __half* batt16 = s16 + (size_t)36*M1;
    __half* bx1_16 = s16 + (size_t)40*M1;
    __half* bx2_16 = s16 + (size_t)44*M1;
    __half* bff16  = s16 + (size_t)48*M1;

    cudaFuncSetAttribute(hgemm16_kernel<false>,
                         cudaFuncAttributeMaxDynamicSharedMemorySize, HG_SMEM);
    cudaFuncSetAttribute(hgemm16_kernel<true>,
                         cudaFuncAttributeMaxDynamicSharedMemorySize, HG_SMEM);

    CvtArgs ca;
    ca.job[0]  = { x,   x16,   4*M1 };
    ca.job[1]  = { mem, mem16, 4*M1 };
    ca.job[2]  = { swq, wq16,  M1 };
    ca.job[3]  = { swk, wk16,  M1 };
    ca.job[4]  = { swv, wv16,  M1 };
    ca.job[5]  = { swo, wo16,  M1 };
    ca.job[6]  = { cwq, cq16,  M1 };
    ca.job[7]  = { cwk, ck16,  M1 };
    ca.job[8]  = { cwv, cv16,  M1 };
    ca.job[9]  = { cwo, co16,  M1 };
    ca.job[10] = { w1,  w1_16, 4*M1 };
    ca.job[11] = { w2,  w2_16, 4*M1 };
    dim3 gCvt(512, 12);
    cvt_kernel<<<gCvt, 256>>>(ca);

    dim3 gP(Dd / 128, RB / 128);
    dim3 gF1(FFf / 128, RB / 128);
    dim3 gAttn(Ll / 64, Bb * Hh);

    // ---- self-attention ----
    hgemm16_kernel<false><<<gP, 256, HG_SMEM>>>(x16, wq16, sbq, nullptr, bq16, Dd, Dd);
    hgemm16_kernel<false><<<gP, 256, HG_SMEM>>>(x16, wk16, sbk, nullptr, bk16, Dd, Dd);
    hgemm16_kernel<false><<<gP, 256, HG_SMEM>>>(x16, wv16, sbv, nullptr, bv16, Dd, Dd);
    attn_mma_kernel<true><<<gAttn, 128>>>(bq16, bk16, bv16, batt16, Ll);
    hgemm16_kernel<false><<<gP, 256, HG_SMEM>>>(batt16, wo16, sbo, btmp, nullptr, Dd, Dd);
    add_ln_kernel<<<RB, 256>>>(x, btmp, g1, be1, bx1, bx1_16);

    // ---- cross-attention ----
    hgemm16_kernel<false><<<gP, 256, HG_SMEM>>>(bx1_16, cq16, cbq, nullptr, bq16, Dd, Dd);
    hgemm16_kernel<false><<<gP, 256, HG_SMEM>>>(mem16, ck16, cbk, nullptr, bk16, Dd, Dd);
    hgemm16_kernel<false><<<gP, 256, HG_SMEM>>>(mem16, cv16, cbv, nullptr, bv16, Dd, Dd);
    attn_mma_kernel<false><<<gAttn, 128>>>(bq16, bk16, bv16, batt16, Mm);
    hgemm16_kernel<false><<<gP, 256, HG_SMEM>>>(batt16, co16, cbo, btmp, nullptr, Dd, Dd);
    add_ln_kernel<<<RB, 256>>>(bx1, btmp, g2, be2, bx2, bx2_16);

    // ---- FFN ----
    hgemm16_kernel<true><<<gF1, 256, HG_SMEM>>>(bx2_16, w1_16, b1, nullptr, bff16, Dd, FFf);
    hgemm16_kernel<false><<<gP, 256, HG_SMEM>>>(bff16, w2_16, b2, btmp, nullptr, FFf, Dd);
    add_ln_kernel<<<RB, 256>>>(bx2, btmp, g3, be3, (float*)d_out, nullptr);
}

// round 13
// speedup vs baseline: 3.6792x; 3.6792x over previous
#include <cuda_runtime.h>
#include <cuda_fp16.h>
#include <cstdint>
#include <math.h>

typedef unsigned int u32;

#define Bb 2
#define Ll 2048
#define Mm 2048
#define Dd 1024
#define Hh 16
#define DHh 64
#define FFf 4096
#define WINW 64
#define RB (Bb*Ll)      // 4096 rows
#define SEG (RB*Dd)     // 4194304

#define M1 (1024*1024)

// fp32 scratch: btmp, bx1, bx2
__device__ float g_f32[(size_t)SEG*3];
// fp16 scratch
__device__ __half g_f16[(size_t)64*M1];

#define CP16(dst, src) asm volatile("cp.async.cg.shared.global [%0], [%1], 16;" :: "r"(dst), "l"(src))
#define CPCOMMIT()     asm volatile("cp.async.commit_group;")

// ---------------------------------------------------------------------------
// Batched fp32 -> fp16 conversion (12 tensors in one launch).
// ---------------------------------------------------------------------------
struct CvtJob { const float* src; __half* dst; int n; };
struct CvtArgs { CvtJob job[12]; };

__global__ __launch_bounds__(256) void cvt_kernel(CvtArgs a) {
    CvtJob j = a.job[blockIdx.y];
    int stride = gridDim.x * 256 * 8;
    for (int base = (blockIdx.x * 256 + threadIdx.x) * 8; base < j.n; base += stride) {
        float4 f0 = *(const float4*)(j.src + base);
        float4 f1 = *(const float4*)(j.src + base + 4);
        __half2 h0 = __floats2half2_rn(f0.x, f0.y);
        __half2 h1 = __floats2half2_rn(f0.z, f0.w);
        __half2 h2 = __floats2half2_rn(f1.x, f1.y);
        __half2 h3 = __floats2half2_rn(f1.z, f1.w);
        uint4 o;
        o.x = *(u32*)&h0; o.y = *(u32*)&h1; o.z = *(u32*)&h2; o.w = *(u32*)&h3;
        *(uint4*)(j.dst + base) = o;
    }
}

// ---------------------------------------------------------------------------
// fp16 tensor-core GEMM. Block tile 128x256x32, 512 threads (16 warps, 2x8),
// warp tile 64x32. 3-stage cp.async ring (72KB dynamic smem, 1 CTA/SM).
// 25% fewer load instructions per FLOP than the 128x128 variant.
// ---------------------------------------------------------------------------
#define NSTAGE 3
#define A_SZ 8192
#define STG_BYTES 24576
#define HG_SMEM (NSTAGE * STG_BYTES)   // 73728

template<bool GELU>
__global__ __launch_bounds__(512, 1) void hgemm16_kernel(
    const __half* __restrict__ A, const __half* __restrict__ Wm,
    const float* __restrict__ bias, float* __restrict__ C32,
    __half* __restrict__ C16, int K, int N)
{
    extern __shared__ __align__(16) unsigned char dsm[];
    const u32 sbase = (u32)__cvta_generic_to_shared(dsm);

    const int tid = threadIdx.x;
    const int lane = tid & 31, wid = tid >> 5;
    const int warp_m = wid >> 3, warp_n = wid & 7;   // 2 x 8 warps
    const int row0 = blockIdx.y * 128, col0 = blockIdx.x * 256;
    const int ntiles = K >> 5;

    float acc[4][4][4];
    #pragma unroll
    for (int i = 0; i < 4; i++)
        #pragma unroll
        for (int j = 0; j < 4; j++)
            #pragma unroll
            for (int q = 0; q < 4; q++) acc[i][j][q] = 0.f;

    // A loader: ar = tid/4 (0..127), ak = tid%4 (16B chunk)
    const int ar = tid >> 2, ak = tid & 3;
    // B loader: br = tid/16 (0..31), chunks 2*(tid%16), +1
    const int br = tid >> 4, bc0 = (tid & 15) << 1;

    const __half* Agp = A + (size_t)(row0 + ar) * K + ak * 8;
    const __half* Bgp = Wm + (size_t)br * N + col0;

    const u32 aDst = sbase + ar * 64 + (((ak) + (ar >> 1)) & 3) * 16;
    const u32 bDst0 = sbase + A_SZ + br * 512 + (((bc0    ) ^ (br & 7)) << 4);
    const u32 bDst1 = sbase + A_SZ + br * 512 + (((bc0 + 1) ^ (br & 7)) << 4);

    // prefetch tiles 0 and 1 into stages 0 and 1
    #pragma unroll
    for (int p = 0; p < 2; p++) {
        u32 off = p * STG_BYTES;
        int k0 = p << 5;
        CP16(aDst + off, Agp + k0);
        CP16(bDst0 + off, Bgp + (size_t)k0 * N + bc0 * 8);
        CP16(bDst1 + off, Bgp + (size_t)k0 * N + bc0 * 8 + 8);
        CPCOMMIT();
    }

    int stage = 0, pstage = 2;
    for (int t = 0; t < ntiles; t++) {
        asm volatile("cp.async.wait_group 1;");
        __syncthreads();

        if (t + 2 < ntiles) {
            u32 off = pstage * STG_BYTES;
            int k0 = (t + 2) << 5;
            CP16(aDst + off, Agp + k0);
            CP16(bDst0 + off, Bgp + (size_t)k0 * N + bc0 * 8);
            CP16(bDst1 + off, Bgp + (size_t)k0 * N + bc0 * 8 + 8);
        }
        CPCOMMIT();

        const u32 sA = sbase + stage * STG_BYTES;
        const u32 sB = sA + A_SZ;

        #pragma unroll
        for (int ks = 0; ks < 2; ks++) {
            u32 af[4][4];
            #pragma unroll
            for (int mt = 0; mt < 4; mt++) {
                int rr = warp_m * 64 + mt * 16 + ((lane >> 3) & 1) * 8 + (lane & 7);
                int cc = ks * 2 + (lane >> 4);
                u32 aaddr = sA + rr * 64 + (((cc + (rr >> 1)) & 3) << 4);
                asm volatile(
                    "ldmatrix.sync.aligned.m8n8.x4.shared.b16 {%0,%1,%2,%3}, [%4];"
                    : "=r"(af[mt][0]), "=r"(af[mt][1]), "=r"(af[mt][2]), "=r"(af[mt][3])
                    : "r"(aaddr));
            }
            #pragma unroll
            for (int nt = 0; nt < 4; nt++) {
                int rr = ks * 16 + (lane & 15);
                int cc = warp_n * 4 + nt;
                u32 baddr = sB + rr * 512 + ((cc ^ (rr & 7)) << 4);
                u32 bf0, bf1;
                asm volatile(
                    "ldmatrix.sync.aligned.m8n8.x2.trans.shared.b16 {%0,%1}, [%2];"
                    : "=r"(bf0), "=r"(bf1) : "r"(baddr));
                #pragma unroll
                for (int mt = 0; mt < 4; mt++) {
                    asm volatile(
                        "mma.sync.aligned.m16n8k16.row.col.f32.f16.f16.f32 "
                        "{%0,%1,%2,%3}, {%4,%5,%6,%7}, {%8,%9}, {%0,%1,%2,%3};"
                        : "+f"(acc[mt][nt][0]), "+f"(acc[mt][nt][1]),
                          "+f"(acc[mt][nt][2]), "+f"(acc[mt][nt][3])
                        : "r"(af[mt][0]), "r"(af[mt][1]), "r"(af[mt][2]), "r"(af[mt][3]),
                          "r"(bf0), "r"(bf1));
                }
            }
        }

        stage = (stage == 2) ? 0 : stage + 1;
        pstage = (pstage == 2) ? 0 : pstage + 1;
    }

    const int g = lane >> 2, tl = lane & 3;
    #pragma unroll
    for (int nt = 0; nt < 4; nt++) {
        int col = col0 + warp_n * 32 + nt * 8 + 2 * tl;
        float2 bb = *(const float2*)&bias[col];
        #pragma unroll
        for (int mt = 0; mt < 4; mt++) {
            int rlo = row0 + warp_m * 64 + mt * 16 + g;
            float2 olo, ohi;
            olo.x = acc[mt][nt][0] + bb.x;
            olo.y = acc[mt][nt][1] + bb.y;
            ohi.x = acc[mt][nt][2] + bb.x;
            ohi.y = acc[mt][nt][3] + bb.y;
            if (GELU) {
                olo.x = 0.5f * olo.x * (1.0f + erff(olo.x * 0.70710678118654752f));
                olo.y = 0.5f * olo.y * (1.0f + erff(olo.y * 0.70710678118654752f));
                ohi.x = 0.5f * ohi.x * (1.0f + erff(ohi.x * 0.70710678118654752f));
                ohi.y = 0.5f * ohi.y * (1.0f + erff(ohi.y * 0.70710678118654752f));
            }
            if (C32) {
                *(float2*)&C32[(size_t)rlo * N + col] = olo;
                *(float2*)&C32[(size_t)(rlo + 8) * N + col] = ohi;
            }
            if (C16) {
                __half2 hlo = __floats2half2_rn(olo.x, olo.y);
                __half2 hhi = __floats2half2_rn(ohi.x, ohi.y);
                *(__half2*)&C16[(size_t)rlo * N + col] = hlo;
                *(__half2*)&C16[(size_t)(rlo + 8) * N + col] = hhi;
            }
        }
    }
}

// ---------------------------------------------------------------------------
// MMA flash attention (unchanged — passing since R5).
// ---------------------------------------------------------------------------
template<bool WINDOWED>
__global__ __launch_bounds__(128) void attn_mma_kernel(
    const __half* __restrict__ q, const __half* __restrict__ k,
    const __half* __restrict__ v, __half* __restrict__ out, int Lk)
{
    __shared__ __align__(16) __half Q_s[64 * 64];
    __shared__ __align__(16) __half K_s[2][64 * 64];
    __shared__ __align__(16) __half V_s[2][64 * 64];

    const int tid = threadIdx.x;
    const int lane = tid & 31, wid = tid >> 5;
    const int b = blockIdx.y >> 4, h = blockIdx.y & 15;
    const int q0 = blockIdx.x * 64;

    const __half* qb = q + (size_t)(b * Ll + q0) * Dd + h * DHh;
    const __half* kb = k + (size_t)b * Lk * Dd + h * DHh;
    const __half* vb = v + (size_t)b * Lk * Dd + h * DHh;

    const u32 sQ  = (u32)__cvta_generic_to_shared(Q_s);
    const u32 sK0 = (u32)__cvta_generic_to_shared(K_s);
    const u32 sV0 = (u32)__cvta_generic_to_shared(V_s);

    const float slope = WINDOWED ? exp2f(-0.5f * (float)(h + 1)) : 0.0f;

    int t0 = 0, t1 = Lk / 64 - 1;
    if (WINDOWED) { t0 = (q0 >> 6) - 1; if (t0 < 0) t0 = 0; t1 = q0 >> 6; }

    const int lr = tid >> 1, lc0 = (tid & 1) * 4;

    #pragma unroll
    for (int c = 0; c < 4; c++) {
        int cc = lc0 + c;
        CP16(sQ + lr * 128 + ((cc ^ (lr & 7)) << 4), qb + (size_t)lr * Dd + cc * 8);
    }
    CPCOMMIT();
    {
        const __half* kr = kb + (size_t)(t0 * 64 + lr) * Dd;
        const __half* vr = vb + (size_t)(t0 * 64 + lr) * Dd;
        #pragma unroll
        for (int c = 0; c < 4; c++) {
            int cc = lc0 + c;
            u32 doff = lr * 128 + ((cc ^ (lr & 7)) << 4);
            CP16(sK0 + doff, kr + cc * 8);
            CP16(sV0 + doff, vr + cc * 8);
        }
        CPCOMMIT();
    }
    asm volatile("cp.async.wait_group 0;");
    __syncthreads();

    u32 qf[4][4];
    #pragma unroll
    for (int ks = 0; ks < 4; ks++) {
        int rr = wid * 16 + ((lane >> 3) & 1) * 8 + (lane & 7);
        int cc = ks * 2 + (lane >> 4);
        u32 addr = sQ + rr * 128 + ((cc ^ (rr & 7)) << 4);
        asm volatile(
            "ldmatrix.sync.aligned.m8n8.x4.shared.b16 {%0,%1,%2,%3}, [%4];"
            : "=r"(qf[ks][0]), "=r"(qf[ks][1]), "=r"(qf[ks][2]), "=r"(qf[ks][3])
            : "r"(addr));
    }

    float m0 = -3.4e38f, m1 = -3.4e38f, l0 = 0.f, l1 = 0.f;
    float oacc[8][4];
    #pragma unroll
    for (int nt = 0; nt < 8; nt++)
        #pragma unroll
        for (int e = 0; e < 4; e++) oacc[nt][e] = 0.f;

    const int qr = lane >> 2;
    const int qc2 = (lane & 3) << 1;

    for (int t = t0; t <= t1; t++) {
        int buf = (t - t0) & 1;
        if (t < t1) {
            u32 off = (buf ^ 1) * 8192;
            const __half* kr = kb + (size_t)((t + 1) * 64 + lr) * Dd;
            const __half* vr = vb + (size_t)((t + 1) * 64 + lr) * Dd;
            #pragma unroll
            for (int c = 0; c < 4; c++) {
                int cc = lc0 + c;
                u32 doff = lr * 128 + ((cc ^ (lr & 7)) << 4);
                CP16(sK0 + off + doff, kr + cc * 8);
                CP16(sV0 + off + doff, vr + cc * 8);
            }
            CPCOMMIT();
            asm volatile("cp.async.wait_group 1;");
        } else {
            asm volatile("cp.async.wait_group 0;");
        }
        __syncthreads();

        const u32 sK = sK0 + buf * 8192;
        const u32 sV = sV0 + buf * 8192;

        float sacc[8][4];
        #pragma unroll
        for (int nt = 0; nt < 8; nt++) {
            sacc[nt][0] = sacc[nt][1] = sacc[nt][2] = sacc[nt][3] = 0.f;
            #pragma unroll
            for (int ks = 0; ks < 4; ks++) {
                int krow = nt * 8 + (lane & 7);
                int cc = ks * 2 + ((lane >> 3) & 1);
                u32 addr = sK + krow * 128 + ((cc ^ (krow & 7)) << 4);
                u32 bf0, bf1;
                asm volatile(
                    "ldmatrix.sync.aligned.m8n8.x2.shared.b16 {%0,%1}, [%2];"
                    : "=r"(bf0), "=r"(bf1) : "r"(addr));
                asm volatile(
                    "mma.sync.aligned.m16n8k16.row.col.f32.f16.f16.f32 "
                    "{%0,%1,%2,%3}, {%4,%5,%6,%7}, {%8,%9}, {%0,%1,%2,%3};"
                    : "+f"(sacc[nt][0]), "+f"(sacc[nt][1]),
                      "+f"(sacc[nt][2]), "+f"(sacc[nt][3])
                    : "r"(qf[ks][0]), "r"(qf[ks][1]), "r"(qf[ks][2]), "r"(qf[ks][3]),
                      "r"(bf0), "r"(bf1));
            }
        }

        float mt0 = -3.4e38f, mt1 = -3.4e38f;
        #pragma unroll
        for (int nt = 0; nt < 8; nt++) {
            #pragma unroll
            for (int e = 0; e < 4; e++) {
                float s = sacc[nt][e] * 0.125f;
                if (WINDOWED) {
                    int i = q0 + wid * 16 + qr + ((e >> 1) << 3);
                    int j = t * 64 + nt * 8 + qc2 + (e & 1);
                    s += slope * (float)(j - i);
                    if (j > i || (i - j) >= WINW) s = -3.4e38f;
                }
                sacc[nt][e] = s;
                if (e < 2) mt0 = fmaxf(mt0, s); else mt1 = fmaxf(mt1, s);
            }
        }
        mt0 = fmaxf(mt0, __shfl_xor_sync(0xffffffffu, mt0, 1));
        mt0 = fmaxf(mt0, __shfl_xor_sync(0xffffffffu, mt0, 2));
        mt1 = fmaxf(mt1, __shfl_xor_sync(0xffffffffu, mt1, 1));
        mt1 = fmaxf(mt1, __shfl_xor_sync(0xffffffffu, mt1, 2));

        float mn0 = fmaxf(m0, mt0), mn1 = fmaxf(m1, mt1);
        bool dead0 = mn0 < -1e37f, dead1 = mn1 < -1e37f;
        float corr0 = dead0 ? 1.f : __expf(m0 - mn0);
        float corr1 = dead1 ? 1.f : __expf(m1 - mn1);

        float ls0 = 0.f, ls1 = 0.f;
        #pragma unroll
        for (int nt = 0; nt < 8; nt++) {
            float p0 = dead0 ? 0.f : __expf(sacc[nt][0] - mn0);
            float p1 = dead0 ? 0.f : __expf(sacc[nt][1] - mn0);
            float p2 = dead1 ? 0.f : __expf(sacc[nt][2] - mn1);
            float p3 = dead1 ? 0.f : __expf(sacc[nt][3] - mn1);
            sacc[nt][0] = p0; sacc[nt][1] = p1; sacc[nt][2] = p2; sacc[nt][3] = p3;
            ls0 += p0 + p1; ls1 += p2 + p3;
        }
        ls0 += __shfl_xor_sync(0xffffffffu, ls0, 1);
        ls0 += __shfl_xor_sync(0xffffffffu, ls0, 2);
        ls1 += __shfl_xor_sync(0xffffffffu, ls1, 1);
        ls1 += __shfl_xor_sync(0xffffffffu, ls1, 2);

        l0 = l0 * corr0 + ls0;
        l1 = l1 * corr1 + ls1;
        m0 = mn0; m1 = mn1;

        #pragma unroll
        for (int nt = 0; nt < 8; nt++) {
            oacc[nt][0] *= corr0; oacc[nt][1] *= corr0;
            oacc[nt][2] *= corr1; oacc[nt][3] *= corr1;
        }

        #pragma unroll
        for (int ks = 0; ks < 4; ks++) {
            __half2 ph0 = __floats2half2_rn(sacc[2*ks][0], sacc[2*ks][1]);
            __half2 ph1 = __floats2half2_rn(sacc[2*ks][2], sacc[2*ks][3]);
            __half2 ph2 = __floats2half2_rn(sacc[2*ks+1][0], sacc[2*ks+1][1]);
            __half2 ph3 = __floats2half2_rn(sacc[2*ks+1][2], sacc[2*ks+1][3]);
            u32 pa0 = *(u32*)&ph0, pa1 = *(u32*)&ph1;
            u32 pa2 = *(u32*)&ph2, pa3 = *(u32*)&ph3;
            #pragma unroll
            for (int nt = 0; nt < 8; nt++) {
                int vrow = ks * 16 + (lane & 15);
                u32 addr = sV + vrow * 128 + ((nt ^ (vrow & 7)) << 4);
                u32 vf0, vf1;
                asm volatile(
                    "ldmatrix.sync.aligned.m8n8.x2.trans.shared.b16 {%0,%1}, [%2];"
                    : "=r"(vf0), "=r"(vf1) : "r"(addr));
                asm volatile(
                    "mma.sync.aligned.m16n8k16.row.col.f32.f16.f16.f32 "
                    "{%0,%1,%2,%3}, {%4,%5,%6,%7}, {%8,%9}, {%0,%1,%2,%3};"
                    : "+f"(oacc[nt][0]), "+f"(oacc[nt][1]),
                      "+f"(oacc[nt][2]), "+f"(oacc[nt][3])
                    : "r"(pa0), "r"(pa1), "r"(pa2), "r"(pa3),
                      "r"(vf0), "r"(vf1));
            }
        }
        __syncthreads();
    }

    float inv0 = 1.0f / l0, inv1 = 1.0f / l1;
    int row_lo = q0 + wid * 16 + qr;
    __half* ob = out + (size_t)(b * Ll) * Dd + h * DHh;
    #pragma unroll
    for (int nt = 0; nt < 8; nt++) {
        __half2 h0 = __floats2half2_rn(oacc[nt][0] * inv0, oacc[nt][1] * inv0);
        __half2 h1 = __floats2half2_rn(oacc[nt][2] * inv1, oacc[nt][3] * inv1);
        *(__half2*)(ob + (size_t)row_lo * Dd + nt * 8 + qc2) = h0;
        *(__half2*)(ob + (size_t)(row_lo + 8) * Dd + nt * 8 + qc2) = h1;
    }
}

// ---------------------------------------------------------------------------
// out = LayerNorm(a + bres) * g + be. Optional fp16 mirror.
// ---------------------------------------------------------------------------
__global__ __launch_bounds__(256) void add_ln_kernel(
    const float* __restrict__ a, const float* __restrict__ bres,
    const float* __restrict__ g, const float* __restrict__ be,
    float* __restrict__ out, __half* __restrict__ out16)
{
    const int row = blockIdx.x;
    const int tid = threadIdx.x;
    const int d4 = tid << 2;

    float4 va = *(const float4*)(a + (size_t)row * Dd + d4);
    float4 vb = *(const float4*)(bres + (size_t)row * Dd + d4);
    float x0 = va.x + vb.x, x1 = va.y + vb.y, x2 = va.z + vb.z, x3 = va.w + vb.w;

    float s = x0 + x1 + x2 + x3;
    float ss = x0 * x0 + x1 * x1 + x2 * x2 + x3 * x3;

    #pragma unroll
    for (int off = 16; off >= 1; off >>= 1) {
        s  += __shfl_down_sync(0xffffffffu, s,  off);
        ss += __shfl_down_sync(0xffffffffu, ss, off);
    }
    __shared__ float rs[8], rss[8];
    __shared__ float s_mu, s_rstd;
    if ((tid & 31) == 0) { rs[tid >> 5] = s; rss[tid >> 5] = ss; }
    __syncthreads();
    if (tid == 0) {
        float S = 0.f, SS = 0.f;
        #pragma unroll
        for (int w = 0; w < 8; w++) { S += rs[w]; SS += rss[w]; }
        float mu = S * (1.0f / Dd);
        float var = SS * (1.0f / Dd) - mu * mu;
        s_mu = mu;
        s_rstd = rsqrtf(var + 1e-5f);
    }
    __syncthreads();
    float mu = s_mu, rstd = s_rstd;

    float4 gg = *(const float4*)(g + d4);
    float4 bb = *(const float4*)(be + d4);
    float4 o;
    o.x = (x0 - mu) * rstd * gg.x + bb.x;
    o.y = (x1 - mu) * rstd * gg.y + bb.y;
    o.z = (x2 - mu) * rstd * gg.z + bb.z;
    o.w = (x3 - mu) * rstd * gg.w + bb.w;
    *(float4*)(out + (size_t)row * Dd + d4) = o;
    if (out16) {
        __half2 h0 = __floats2half2_rn(o.x, o.y);
        __half2 h1 = __floats2half2_rn(o.z, o.w);
        uint2 ho; ho.x = *(u32*)&h0; ho.y = *(u32*)&h1;
        *(uint2*)(out16 + (size_t)row * Dd + d4) = ho;
    }
}

// ---------------------------------------------------------------------------
extern "C" void kernel_launch(void* const* d_in, const int* in_sizes, int n_in,
                              void* d_out, int out_size)
{
    const float* x   = (const float*)d_in[0];
    const float* mem = (const float*)d_in[1];

    const float *swq, *sbq, *swk, *sbk, *swv, *sbv, *swo, *sbo;
    const float *cwq, *cbq, *cwk, *cbk, *cwv, *cbv, *cwo, *cbo;
    const float *w1, *b1, *w2, *b2, *g1, *be1, *g2, *be2, *g3, *be3;

    if (in_sizes[3] == Dd) {
        swq=(const float*)d_in[2];  sbq=(const float*)d_in[3];
        swk=(const float*)d_in[4];  sbk=(const float*)d_in[5];
        swv=(const float*)d_in[6];  sbv=(const float*)d_in[7];
        swo=(const float*)d_in[8];  sbo=(const float*)d_in[9];
        cwq=(const float*)d_in[10]; cbq=(const float*)d_in[11];
        cwk=(const float*)d_in[12]; cbk=(const float*)d_in[13];
        cwv=(const float*)d_in[14]; cbv=(const float*)d_in[15];
        cwo=(const float*)d_in[16]; cbo=(const float*)d_in[17];
        w1=(const float*)d_in[18];  b1=(const float*)d_in[19];
        w2=(const float*)d_in[20];  b2=(const float*)d_in[21];
        g1=(const float*)d_in[22];  be1=(const float*)d_in[23];
        g2=(const float*)d_in[24];  be2=(const float*)d_in[25];
        g3=(const float*)d_in[26];  be3=(const float*)d_in[27];
    } else {
        swq=(const float*)d_in[2];  swk=(const float*)d_in[3];
        swv=(const float*)d_in[4];  swo=(const float*)d_in[5];
        sbq=(const float*)d_in[6];  sbk=(const float*)d_in[7];
        sbv=(const float*)d_in[8];  sbo=(const float*)d_in[9];
        cwq=(const float*)d_in[10]; cwk=(const float*)d_in[11];
        cwv=(const float*)d_in[12]; cwo=(const float*)d_in[13];
        cbq=(const float*)d_in[14]; cbk=(const float*)d_in[15];
        cbv=(const float*)d_in[16]; cbo=(const float*)d_in[17];
        w1=(const float*)d_in[18];  b1=(const float*)d_in[19];
        w2=(const float*)d_in[20];  b2=(const float*)d_in[21];
        g1=(const float*)d_in[22];  g2=(const float*)d_in[23];
        g3=(const float*)d_in[24];
        be1=(const float*)d_in[25]; be2=(const float*)d_in[26];
        be3=(const float*)d_in[27];
    }

    float* s32 = nullptr;
    cudaGetSymbolAddress((void**)&s32, g_f32);
    __half* s16 = nullptr;
    cudaGetSymbolAddress((void**)&s16, g_f16);

    float* btmp = s32;
    float* bx1  = s32 + (size_t)SEG;
    float* bx2  = s32 + (size_t)SEG * 2;

    __half* x16    = s16;
    __half* mem16  = s16 + (size_t)4*M1;
    __half* wq16   = s16 + (size_t)8*M1;
    __half* wk16   = s16 + (size_t)9*M1;
    __half* wv16   = s16 + (size_t)10*M1;
    __half* wo16   = s16 + (size_t)11*M1;
    __half* cq16   = s16 + (size_t)12*M1;
    __half* ck16   = s16 + (size_t)13*M1;
    __half* cv16   = s16 + (size_t)14*M1;
    __half* co16   = s16 + (size_t)15*M1;
    __half* w1_16  = s16 + (size_t)16*M1;
    __half* w2_16  = s16 + (size_t)20*M1;
    __half* bq16   = s16 + (size_t)24*M1;
    __half* bk16   = s16 + (size_t)28*M1;
    __half* bv16   = s16 + (size_t)32*M1;
    __half* batt16 = s16 + (size_t)36*M1;
    __half* bx1_16 = s16 + (size_t)40*M1;
    __half* bx2_16 = s16 + (size_t)44*M1;
    __half* bff16  = s16 + (size_t)48*M1;

    cudaFuncSetAttribute(hgemm16_kernel<false>,
                         cudaFuncAttributeMaxDynamicSharedMemorySize, HG_SMEM);
    cudaFuncSetAttribute(hgemm16_kernel<true>,
                         cudaFuncAttributeMaxDynamicSharedMemorySize, HG_SMEM);

    CvtArgs ca;
    ca.job[0]  = { x,   x16,   4*M1 };
    ca.job[1]  = { mem, mem16, 4*M1 };
    ca.job[2]  = { swq, wq16,  M1 };
    ca.job[3]  = { swk, wk16,  M1 };
    ca.job[4]  = { swv, wv16,  M1 };
    ca.job[5]  = { swo, wo16,  M1 };
    ca.job[6]  = { cwq, cq16,  M1 };
    ca.job[7]  = { cwk, ck16,  M1 };
    ca.job[8]  = { cwv, cv16,  M1 };
    ca.job[9]  = { cwo, co16,  M1 };
    ca.job[10] = { w1,  w1_16, 4*M1 };
    ca.job[11] = { w2,  w2_16, 4*M1 };
    dim3 gCvt(512, 12);
    cvt_kernel<<<gCvt, 256>>>(ca);

    dim3 gP(Dd / 256, RB / 128);     // (4, 32)
    dim3 gF1(FFf / 256, RB / 128);   // (16, 32)
    dim3 gAttn(Ll / 64, Bb * Hh);

    // ---- self-attention ----
    hgemm16_kernel<false><<<gP, 512, HG_SMEM>>>(x16, wq16, sbq, nullptr, bq16, Dd, Dd);
    hgemm16_kernel<false><<<gP, 512, HG_SMEM>>>(x16, wk16, sbk, nullptr, bk16, Dd, Dd);
    hgemm16_kernel<false><<<gP, 512, HG_SMEM>>>(x16, wv16, sbv, nullptr, bv16, Dd, Dd);
    attn_mma_kernel<true><<<gAttn, 128>>>(bq16, bk16, bv16, batt16, Ll);
    hgemm16_kernel<false><<<gP, 512, HG_SMEM>>>(batt16, wo16, sbo, btmp, nullptr, Dd, Dd);
    add_ln_kernel<<<RB, 256>>>(x, btmp, g1, be1, bx1, bx1_16);

    // ---- cross-attention ----
    hgemm16_kernel<false><<<gP, 512, HG_SMEM>>>(bx1_16, cq16, cbq, nullptr, bq16, Dd, Dd);
    hgemm16_kernel<false><<<gP, 512, HG_SMEM>>>(mem16, ck16, cbk, nullptr, bk16, Dd, Dd);
    hgemm16_kernel<false><<<gP, 512, HG_SMEM>>>(mem16, cv16, cbv, nullptr, bv16, Dd, Dd);
    attn_mma_kernel<false><<<gAttn, 128>>>(bq16, bk16, bv16, batt16, Mm);
    hgemm16_kernel<false><<<gP, 512, HG_SMEM>>>(batt16, co16, cbo, btmp, nullptr, Dd, Dd);
    add_ln_kernel<<<RB, 256>>>(bx1, btmp, g2, be2, bx2, bx2_16);

    // ---- FFN ----
    hgemm16_kernel<true><<<gF1, 512, HG_SMEM>>>(bx2_16, w1_16, b1, nullptr, bff16, Dd, FFf);
    hgemm16_kernel<false><<<gP, 512, HG_SMEM>>>(bff16, w2_16, b2, btmp, nullptr, FFf, Dd);
    add_ln_kernel<<<RB, 256>>>(bx2, btmp, g3, be3, (float*)d_out, nullptr);
}

// round 15
// speedup vs baseline: 3.8926x; 1.0580x over previous
#include <cuda_runtime.h>
#include <cuda_fp16.h>
#include <cstdint>
#include <math.h>

typedef unsigned int u32;

#define Bb 2
#define Ll 2048
#define Mm 2048
#define Dd 1024
#define Hh 16
#define DHh 64
#define FFf 4096
#define WINW 64
#define RB (Bb*Ll)      // 4096 rows
#define SEG (RB*Dd)     // 4194304

#define M1 (1024*1024)

// fp32 scratch: btmp, bx1, bx2
__device__ float g_f32[(size_t)SEG*3];
// fp16 scratch (76 M1 halfs)
__device__ __half g_f16[(size_t)76*M1];

#define CP16(dst, src) asm volatile("cp.async.cg.shared.global [%0], [%1], 16;" :: "r"(dst), "l"(src))
#define CPCOMMIT()     asm volatile("cp.async.commit_group;")

// ---------------------------------------------------------------------------
// Batched fp32 -> fp16 conversion (12 tensors in one launch).
// ---------------------------------------------------------------------------
struct CvtJob { const float* src; __half* dst; int n; };
struct CvtArgs { CvtJob job[12]; };

__global__ __launch_bounds__(256) void cvt_kernel(CvtArgs a) {
    CvtJob j = a.job[blockIdx.y];
    int stride = gridDim.x * 256 * 8;
    for (int base = (blockIdx.x * 256 + threadIdx.x) * 8; base < j.n; base += stride) {
        float4 f0 = *(const float4*)(j.src + base);
        float4 f1 = *(const float4*)(j.src + base + 4);
        __half2 h0 = __floats2half2_rn(f0.x, f0.y);
        __half2 h1 = __floats2half2_rn(f0.z, f0.w);
        __half2 h2 = __floats2half2_rn(f1.x, f1.y);
        __half2 h3 = __floats2half2_rn(f1.z, f1.w);
        uint4 o;
        o.x = *(u32*)&h0; o.y = *(u32*)&h1; o.z = *(u32*)&h2; o.w = *(u32*)&h3;
        *(uint4*)(j.dst + base) = o;
    }
}

// ---------------------------------------------------------------------------
// Core fp16 tensor-core GEMM body (exact R10 best-passing version).
// 3-stage cp.async ring, 128x128x32 tile, 8 warps, operand-prefetch loop.
// ---------------------------------------------------------------------------
template<bool GELU>
__device__ __forceinline__ void hgemm_body(
    const __half* __restrict__ A, const __half* __restrict__ Wm,
    const float* __restrict__ bias, float* __restrict__ C32,
    __half* __restrict__ C16, int K, int N,
    int row0, int col0, unsigned char* smem_buf)
{
    const int tid = threadIdx.x;
    const int lane = tid & 31, wid = tid >> 5;
    const int warp_m = wid >> 2, warp_n = wid & 3;
    const u32 sbase = (u32)__cvta_generic_to_shared(smem_buf);

    float acc[4][4][4];
    #pragma unroll
    for (int i = 0; i < 4; i++)
        #pragma unroll
        for (int j = 0; j < 4; j++)
            #pragma unroll
            for (int q = 0; q < 4; q++) acc[i][j][q] = 0.f;

    const int ar = tid >> 1, akh = tid & 1;
    const int br = tid >> 3, bnh = tid & 7;

    const __half* Agp = A + (size_t)(row0 + ar) * K + akh * 16;
    const __half* Bgp = Wm + (size_t)br * N + col0 + bnh * 16;

    const u32 aDst0 = sbase + ar * 64 + (((2 * akh    ) + (ar >> 1)) & 3) * 16;
    const u32 aDst1 = sbase + ar * 64 + (((2 * akh + 1) + (ar >> 1)) & 3) * 16;
    const u32 bDst0 = sbase + 8192 + br * 256 + (((2 * bnh    ) ^ (br & 7))) * 16;
    const u32 bDst1 = sbase + 8192 + br * 256 + (((2 * bnh + 1) ^ (br & 7))) * 16;

    const int ntiles = K >> 5;

    #pragma unroll
    for (int p = 0; p < 2; p++) {
        u32 off = p * 16384;
        int k0 = p << 5;
        CP16(aDst0 + off, Agp + k0);
        CP16(aDst1 + off, Agp + k0 + 8);
        CP16(bDst0 + off, Bgp + (size_t)k0 * N);
        CP16(bDst1 + off, Bgp + (size_t)k0 * N + 8);
        CPCOMMIT();
    }

    int stage = 0, pstage = 2;
    for (int t = 0; t < ntiles; t++) {
        asm volatile("cp.async.wait_group 1;");
        __syncthreads();

        if (t + 2 < ntiles) {
            u32 off = pstage * 16384;
            int k0 = (t + 2) << 5;
            CP16(aDst0 + off, Agp + k0);
            CP16(aDst1 + off, Agp + k0 + 8);
            CP16(bDst0 + off, Bgp + (size_t)k0 * N);
            CP16(bDst1 + off, Bgp + (size_t)k0 * N + 8);
        }
        CPCOMMIT();

        const u32 sA = sbase + stage * 16384;
        const u32 sB = sA + 8192;

        #pragma unroll
        for (int ks = 0; ks < 2; ks++) {
            u32 af[4][4];
            #pragma unroll
            for (int mt = 0; mt < 4; mt++) {
                int rr = warp_m * 64 + mt * 16 + ((lane >> 3) & 1) * 8 + (lane & 7);
                int cc = ks * 2 + (lane >> 4);
                u32 aaddr = sA + rr * 64 + (((cc + (rr >> 1)) & 3) << 4);
                asm volatile(
                    "ldmatrix.sync.aligned.m8n8.x4.shared.b16 {%0,%1,%2,%3}, [%4];"
                    : "=r"(af[mt][0]), "=r"(af[mt][1]), "=r"(af[mt][2]), "=r"(af[mt][3])
                    : "r"(aaddr));
            }
            u32 bf[4][2];
            #pragma unroll
            for (int nt = 0; nt < 4; nt++) {
                int rr = ks * 16 + (lane & 15);
                int cc = warp_n * 4 + nt;
                u32 baddr = sB + rr * 256 + ((cc ^ (rr & 7)) << 4);
                asm volatile(
                    "ldmatrix.sync.aligned.m8n8.x2.trans.shared.b16 {%0,%1}, [%2];"
                    : "=r"(bf[nt][0]), "=r"(bf[nt][1]) : "r"(baddr));
            }
            #pragma unroll
            for (int nt = 0; nt < 4; nt++) {
                #pragma unroll
                for (int mt = 0; mt < 4; mt++) {
                    asm volatile(
                        "mma.sync.aligned.m16n8k16.row.col.f32.f16.f16.f32 "
                        "{%0,%1,%2,%3}, {%4,%5,%6,%7}, {%8,%9}, {%0,%1,%2,%3};"
                        : "+f"(acc[mt][nt][0]), "+f"(acc[mt][nt][1]),
                          "+f"(acc[mt][nt][2]), "+f"(acc[mt][nt][3])
                        : "r"(af[mt][0]), "r"(af[mt][1]), "r"(af[mt][2]), "r"(af[mt][3]),
                          "r"(bf[nt][0]), "r"(bf[nt][1]));
                }
            }
        }

        stage = (stage == 2) ? 0 : stage + 1;
        pstage = (pstage == 2) ? 0 : pstage + 1;
    }

    const int g = lane >> 2, tl = lane & 3;
    #pragma unroll
    for (int nt = 0; nt < 4; nt++) {
        int col = col0 + warp_n * 32 + nt * 8 + 2 * tl;
        float2 bb = *(const float2*)&bias[col];
        #pragma unroll
        for (int mt = 0; mt < 4; mt++) {
            int rlo = row0 + warp_m * 64 + mt * 16 + g;
            float2 olo, ohi;
            olo.x = acc[mt][nt][0] + bb.x;
            olo.y = acc[mt][nt][1] + bb.y;
            ohi.x = acc[mt][nt][2] + bb.x;
            ohi.y = acc[mt][nt][3] + bb.y;
            if (GELU) {
                olo.x = 0.5f * olo.x * (1.0f + erff(olo.x * 0.70710678118654752f));
                olo.y = 0.5f * olo.y * (1.0f + erff(olo.y * 0.70710678118654752f));
                ohi.x = 0.5f * ohi.x * (1.0f + erff(ohi.x * 0.70710678118654752f));
                ohi.y = 0.5f * ohi.y * (1.0f + erff(ohi.y * 0.70710678118654752f));
            }
            if (C32) {
                *(float2*)&C32[(size_t)rlo * N + col] = olo;
                *(float2*)&C32[(size_t)(rlo + 8) * N + col] = ohi;
            }
            if (C16) {
                __half2 hlo = __floats2half2_rn(olo.x, olo.y);
                __half2 hhi = __floats2half2_rn(ohi.x, ohi.y);
                *(__half2*)&C16[(size_t)rlo * N + col] = hlo;
                *(__half2*)&C16[(size_t)(rlo + 8) * N + col] = hhi;
            }
        }
    }
}

// single-GEMM wrapper
template<bool GELU>
__global__ __launch_bounds__(256, 2) void hgemm16_kernel(
    const __half* __restrict__ A, const __half* __restrict__ Wm,
    const float* __restrict__ bias, float* __restrict__ C32,
    __half* __restrict__ C16, int K, int N)
{
    __shared__ __align__(16) unsigned char smem_buf[3 * 16384];
    hgemm_body<GELU>(A, Wm, bias, C32, C16, K, N,
                     blockIdx.y * 128, blockIdx.x * 128, smem_buf);
}

// batched wrapper: blockIdx.z selects one of 5 independent DxD GEMMs
struct GemmJob { const __half* A; const __half* W; const float* bias; __half* C; };
struct Gemm5Args { GemmJob job[5]; };

__global__ __launch_bounds__(256, 2) void hgemm16_b5_kernel(Gemm5Args a) {
    __shared__ __align__(16) unsigned char smem_buf[3 * 16384];
    GemmJob j = a.job[blockIdx.z];
    hgemm_body<false>(j.A, j.W, j.bias, nullptr, j.C, Dd, Dd,
                      blockIdx.y * 128, blockIdx.x * 128, smem_buf);
}

// ---------------------------------------------------------------------------
// MMA flash attention (unchanged — passing since R5).
// ---------------------------------------------------------------------------
template<bool WINDOWED>
__global__ __launch_bounds__(128) void attn_mma_kernel(
    const __half* __restrict__ q, const __half* __restrict__ k,
    const __half* __restrict__ v, __half* __restrict__ out, int Lk)
{
    __shared__ __align__(16) __half Q_s[64 * 64];
    __shared__ __align__(16) __half K_s[2][64 * 64];
    __shared__ __align__(16) __half V_s[2][64 * 64];

    const int tid = threadIdx.x;
    const int lane = tid & 31, wid = tid >> 5;
    const int b = blockIdx.y >> 4, h = blockIdx.y & 15;
    const int q0 = blockIdx.x * 64;

    const __half* qb = q + (size_t)(b * Ll + q0) * Dd + h * DHh;
    const __half* kb = k + (size_t)b * Lk * Dd + h * DHh;
    const __half* vb = v + (size_t)b * Lk * Dd + h * DHh;

    const u32 sQ  = (u32)__cvta_generic_to_shared(Q_s);
    const u32 sK0 = (u32)__cvta_generic_to_shared(K_s);
    const u32 sV0 = (u32)__cvta_generic_to_shared(V_s);

    const float slope = WINDOWED ? exp2f(-0.5f * (float)(h + 1)) : 0.0f;

    int t0 = 0, t1 = Lk / 64 - 1;
    if (WINDOWED) { t0 = (q0 >> 6) - 1; if (t0 < 0) t0 = 0; t1 = q0 >> 6; }

    const int lr = tid >> 1, lc0 = (tid & 1) * 4;

    #pragma unroll
    for (int c = 0; c < 4; c++) {
        int cc = lc0 + c;
        CP16(sQ + lr * 128 + ((cc ^ (lr & 7)) << 4), qb + (size_t)lr * Dd + cc * 8);
    }
    CPCOMMIT();
    {
        const __half* kr = kb + (size_t)(t0 * 64 + lr) * Dd;
        const __half* vr = vb + (size_t)(t0 * 64 + lr) * Dd;
        #pragma unroll
        for (int c = 0; c < 4; c++) {
            int cc = lc0 + c;
            u32 doff = lr * 128 + ((cc ^ (lr & 7)) << 4);
            CP16(sK0 + doff, kr + cc * 8);
            CP16(sV0 + doff, vr + cc * 8);
        }
        CPCOMMIT();
    }
    asm volatile("cp.async.wait_group 0;");
    __syncthreads();

    u32 qf[4][4];
    #pragma unroll
    for (int ks = 0; ks < 4; ks++) {
        int rr = wid * 16 + ((lane >> 3) & 1) * 8 + (lane & 7);
        int cc = ks * 2 + (lane >> 4);
        u32 addr = sQ + rr * 128 + ((cc ^ (rr & 7)) << 4);
        asm volatile(
            "ldmatrix.sync.aligned.m8n8.x4.shared.b16 {%0,%1,%2,%3}, [%4];"
            : "=r"(qf[ks][0]), "=r"(qf[ks][1]), "=r"(qf[ks][2]), "=r"(qf[ks][3])
            : "r"(addr));
    }

    float m0 = -3.4e38f, m1 = -3.4e38f, l0 = 0.f, l1 = 0.f;
    float oacc[8][4];
    #pragma unroll
    for (int nt = 0; nt < 8; nt++)
        #pragma unroll
        for (int e = 0; e < 4; e++) oacc[nt][e] = 0.f;

    const int qr = lane >> 2;
    const int qc2 = (lane & 3) << 1;

    for (int t = t0; t <= t1; t++) {
        int buf = (t - t0) & 1;
        if (t < t1) {
            u32 off = (buf ^ 1) * 8192;
            const __half* kr = kb + (size_t)((t + 1) * 64 + lr) * Dd;
            const __half* vr = vb + (size_t)((t + 1) * 64 + lr) * Dd;
            #pragma unroll
            for (int c = 0; c < 4; c++) {
                int cc = lc0 + c;
                u32 doff = lr * 128 + ((cc ^ (lr & 7)) << 4);
                CP16(sK0 + off + doff, kr + cc * 8);
                CP16(sV0 + off + doff, vr + cc * 8);
            }
            CPCOMMIT();
            asm volatile("cp.async.wait_group 1;");
        } else {
            asm volatile("cp.async.wait_group 0;");
        }
        __syncthreads();

        const u32 sK = sK0 + buf * 8192;
        const u32 sV = sV0 + buf * 8192;

        float sacc[8][4];
        #pragma unroll
        for (int nt = 0; nt < 8; nt++) {
            sacc[nt][0] = sacc[nt][1] = sacc[nt][2] = sacc[nt][3] = 0.f;
            #pragma unroll
            for (int ks = 0; ks < 4; ks++) {
                int krow = nt * 8 + (lane & 7);
                int cc = ks * 2 + ((lane >> 3) & 1);
                u32 addr = sK + krow * 128 + ((cc ^ (krow & 7)) << 4);
                u32 bf0, bf1;
                asm volatile(
                    "ldmatrix.sync.aligned.m8n8.x2.shared.b16 {%0,%1}, [%2];"
                    : "=r"(bf0), "=r"(bf1) : "r"(addr));
                asm volatile(
                    "mma.sync.aligned.m16n8k16.row.col.f32.f16.f16.f32 "
                    "{%0,%1,%2,%3}, {%4,%5,%6,%7}, {%8,%9}, {%0,%1,%2,%3};"
                    : "+f"(sacc[nt][0]), "+f"(sacc[nt][1]),
                      "+f"(sacc[nt][2]), "+f"(sacc[nt][3])
                    : "r"(qf[ks][0]), "r"(qf[ks][1]), "r"(qf[ks][2]), "r"(qf[ks][3]),
                      "r"(bf0), "r"(bf1));
            }
        }

        float mt0 = -3.4e38f, mt1 = -3.4e38f;
        #pragma unroll
        for (int nt = 0; nt < 8; nt++) {
            #pragma unroll
            for (int e = 0; e < 4; e++) {
                float s = sacc[nt][e] * 0.125f;
                if (WINDOWED) {
                    int i = q0 + wid * 16 + qr + ((e >> 1) << 3);
                    int j = t * 64 + nt * 8 + qc2 + (e & 1);
                    s += slope * (float)(j - i);
                    if (j > i || (i - j) >= WINW) s = -3.4e38f;
                }
                sacc[nt][e] = s;
                if (e < 2) mt0 = fmaxf(mt0, s); else mt1 = fmaxf(mt1, s);
            }
        }
        mt0 = fmaxf(mt0, __shfl_xor_sync(0xffffffffu, mt0, 1));
        mt0 = fmaxf(mt0, __shfl_xor_sync(0xffffffffu, mt0, 2));
        mt1 = fmaxf(mt1, __shfl_xor_sync(0xffffffffu, mt1, 1));
        mt1 = fmaxf(mt1, __shfl_xor_sync(0xffffffffu, mt1, 2));

        float mn0 = fmaxf(m0, mt0), mn1 = fmaxf(m1, mt1);
        bool dead0 = mn0 < -1e37f, dead1 = mn1 < -1e37f;
        float corr0 = dead0 ? 1.f : __expf(m0 - mn0);
        float corr1 = dead1 ? 1.f : __expf(m1 - mn1);

        float ls0 = 0.f, ls1 = 0.f;
        #pragma unroll
        for (int nt = 0; nt < 8; nt++) {
            float p0 = dead0 ? 0.f : __expf(sacc[nt][0] - mn0);
            float p1 = dead0 ? 0.f : __expf(sacc[nt][1] - mn0);
            float p2 = dead1 ? 0.f : __expf(sacc[nt][2] - mn1);
            float p3 = dead1 ? 0.f : __expf(sacc[nt][3] - mn1);
            sacc[nt][0] = p0; sacc[nt][1] = p1; sacc[nt][2] = p2; sacc[nt][3] = p3;
            ls0 += p0 + p1; ls1 += p2 + p3;
        }
        ls0 += __shfl_xor_sync(0xffffffffu, ls0, 1);
        ls0 += __shfl_xor_sync(0xffffffffu, ls0, 2);
        ls1 += __shfl_xor_sync(0xffffffffu, ls1, 1);
        ls1 += __shfl_xor_sync(0xffffffffu, ls1, 2);

        l0 = l0 * corr0 + ls0;
        l1 = l1 * corr1 + ls1;
        m0 = mn0; m1 = mn1;

        #pragma unroll
        for (int nt = 0; nt < 8; nt++) {
            oacc[nt][0] *= corr0; oacc[nt][1] *= corr0;
            oacc[nt][2] *= corr1; oacc[nt][3] *= corr1;
        }

        #pragma unroll
        for (int ks = 0; ks < 4; ks++) {
            __half2 ph0 = __floats2half2_rn(sacc[2*ks][0], sacc[2*ks][1]);
            __half2 ph1 = __floats2half2_rn(sacc[2*ks][2], sacc[2*ks][3]);
            __half2 ph2 = __floats2half2_rn(sacc[2*ks+1][0], sacc[2*ks+1][1]);
            __half2 ph3 = __floats2half2_rn(sacc[2*ks+1][2], sacc[2*ks+1][3]);
            u32 pa0 = *(u32*)&ph0, pa1 = *(u32*)&ph1;
            u32 pa2 = *(u32*)&ph2, pa3 = *(u32*)&ph3;
            #pragma unroll
            for (int nt = 0; nt < 8; nt++) {
                int vrow = ks * 16 + (lane & 15);
                u32 addr = sV + vrow * 128 + ((nt ^ (vrow & 7)) << 4);
                u32 vf0, vf1;
                asm volatile(
                    "ldmatrix.sync.aligned.m8n8.x2.trans.shared.b16 {%0,%1}, [%2];"
                    : "=r"(vf0), "=r"(vf1) : "r"(addr));
                asm volatile(
                    "mma.sync.aligned.m16n8k16.row.col.f32.f16.f16.f32 "
                    "{%0,%1,%2,%3}, {%4,%5,%6,%7}, {%8,%9}, {%0,%1,%2,%3};"
                    : "+f"(oacc[nt][0]), "+f"(oacc[nt][1]),
                      "+f"(oacc[nt][2]), "+f"(oacc[nt][3])
                    : "r"(pa0), "r"(pa1), "r"(pa2), "r"(pa3),
                      "r"(vf0), "r"(vf1));
            }
        }
        __syncthreads();
    }

    float inv0 = 1.0f / l0, inv1 = 1.0f / l1;
    int row_lo = q0 + wid * 16 + qr;
    __half* ob = out + (size_t)(b * Ll) * Dd + h * DHh;
    #pragma unroll
    for (int nt = 0; nt < 8; nt++) {
        __half2 h0 = __floats2half2_rn(oacc[nt][0] * inv0, oacc[nt][1] * inv0);
        __half2 h1 = __floats2half2_rn(oacc[nt][2] * inv1, oacc[nt][3] * inv1);
        *(__half2*)(ob + (size_t)row_lo * Dd + nt * 8 + qc2) = h0;
        *(__half2*)(ob + (size_t)(row_lo + 8) * Dd + nt * 8 + qc2) = h1;
    }
}

// ---------------------------------------------------------------------------
// out = LayerNorm(a + bres) * g + be. Optional fp16 mirror.
// ---------------------------------------------------------------------------
__global__ __launch_bounds__(256) void add_ln_kernel(
    const float* __restrict__ a, const float* __restrict__ bres,
    const float* __restrict__ g, const float* __restrict__ be,
    float* __restrict__ out, __half* __restrict__ out16)
{
    const int row = blockIdx.x;
    const int tid = threadIdx.x;
    const int d4 = tid << 2;

    float4 va = *(const float4*)(a + (size_t)row * Dd + d4);
    float4 vb = *(const float4*)(bres + (size_t)row * Dd + d4);
    float x0 = va.x + vb.x, x1 = va.y + vb.y, x2 = va.z + vb.z, x3 = va.w + vb.w;

    float s = x0 + x1 + x2 + x3;
    float ss = x0 * x0 + x1 * x1 + x2 * x2 + x3 * x3;

    #pragma unroll
    for (int off = 16; off >= 1; off >>= 1) {
        s  += __shfl_down_sync(0xffffffffu, s,  off);
        ss += __shfl_down_sync(0xffffffffu, ss, off);
    }
    __shared__ float rs[8], rss[8];
    __shared__ float s_mu, s_rstd;
    if ((tid & 31) == 0) { rs[tid >> 5] = s; rss[tid >> 5] = ss; }
    __syncthreads();
    if (tid == 0) {
        float S = 0.f, SS = 0.f;
        #pragma unroll
        for (int w = 0; w < 8; w++) { S += rs[w]; SS += rss[w]; }
        float mu = S * (1.0f / Dd);
        float var = SS * (1.0f / Dd) - mu * mu;
        s_mu = mu;
        s_rstd = rsqrtf(var + 1e-5f);
    }
    __syncthreads();
    float mu = s_mu, rstd = s_rstd;

    float4 gg = *(const float4*)(g + d4);
    float4 bb = *(const float4*)(be + d4);
    float4 o;
    o.x = (x0 - mu) * rstd * gg.x + bb.x;
    o.y = (x1 - mu) * rstd * gg.y + bb.y;
    o.z = (x2 - mu) * rstd * gg.z + bb.z;
    o.w = (x3 - mu) * rstd * gg.w + bb.w;
    *(float4*)(out + (size_t)row * Dd + d4) = o;
    if (out16) {
        __half2 h0 = __floats2half2_rn(o.x, o.y);
        __half2 h1 = __floats2half2_rn(o.z, o.w);
        uint2 ho; ho.x = *(u32*)&h0; ho.y = *(u32*)&h1;
        *(uint2*)(out16 + (size_t)row * Dd + d4) = ho;
    }
}

// ---------------------------------------------------------------------------
extern "C" void kernel_launch(void* const* d_in, const int* in_sizes, int n_in,
                              void* d_out, int out_size)
{
    const float* x   = (const float*)d_in[0];
    const float* mem = (const float*)d_in[1];

    const float *swq, *sbq, *swk, *sbk, *swv, *sbv, *swo, *sbo;
    const float *cwq, *cbq, *cwk, *cbk, *cwv, *cbv, *cwo, *cbo;
    const float *w1, *b1, *w2, *b2, *g1, *be1, *g2, *be2, *g3, *be3;

    if (in_sizes[3] == Dd) {
        swq=(const float*)d_in[2];  sbq=(const float*)d_in[3];
        swk=(const float*)d_in[4];  sbk=(const float*)d_in[5];
        swv=(const float*)d_in[6];  sbv=(const float*)d_in[7];
        swo=(const float*)d_in[8];  sbo=(const float*)d_in[9];
        cwq=(const float*)d_in[10]; cbq=(const float*)d_in[11];
        cwk=(const float*)d_in[12]; cbk=(const float*)d_in[13];
        cwv=(const float*)d_in[14]; cbv=(const float*)d_in[15];
        cwo=(const float*)d_in[16]; cbo=(const float*)d_in[17];
        w1=(const float*)d_in[18];  b1=(const float*)d_in[19];
        w2=(const float*)d_in[20];  b2=(const float*)d_in[21];
        g1=(const float*)d_in[22];  be1=(const float*)d_in[23];
        g2=(const float*)d_in[24];  be2=(const float*)d_in[25];
        g3=(const float*)d_in[26];  be3=(const float*)d_in[27];
    } else {
        swq=(const float*)d_in[2];  swk=(const float*)d_in[3];
        swv=(const float*)d_in[4];  swo=(const float*)d_in[5];
        sbq=(const float*)d_in[6];  sbk=(const float*)d_in[7];
        sbv=(const float*)d_in[8];  sbo=(const float*)d_in[9];
        cwq=(const float*)d_in[10]; cwk=(const float*)d_in[11];
        cwv=(const float*)d_in[12]; cwo=(const float*)d_in[13];
        cbq=(const float*)d_in[14]; cbk=(const float*)d_in[15];
        cbv=(const float*)d_in[16]; cbo=(const float*)d_in[17];
        w1=(const float*)d_in[18];  b1=(const float*)d_in[19];
        w2=(const float*)d_in[20];  b2=(const float*)d_in[21];
        g1=(const float*)d_in[22];  g2=(const float*)d_in[23];
        g3=(const float*)d_in[24];
        be1=(const float*)d_in[25]; be2=(const float*)d_in[26];
        be3=(const float*)d_in[27];
    }

    float* s32 = nullptr;
    cudaGetSymbolAddress((void**)&s32, g_f32);
    __half* s16 = nullptr;
    cudaGetSymbolAddress((void**)&s16, g_f16);

    float* btmp = s32;
    float* bx1  = s32 + (size_t)SEG;
    float* bx2  = s32 + (size_t)SEG * 2;

    __half* x16    = s16;
    __half* mem16  = s16 + (size_t)4*M1;
    __half* wq16   = s16 + (size_t)8*M1;
    __half* wk16   = s16 + (size_t)9*M1;
    __half* wv16   = s16 + (size_t)10*M1;
    __half* wo16   = s16 + (size_t)11*M1;
    __half* cq16   = s16 + (size_t)12*M1;
    __half* ck16   = s16 + (size_t)13*M1;
    __half* cv16   = s16 + (size_t)14*M1;
    __half* co16   = s16 + (size_t)15*M1;
    __half* w1_16  = s16 + (size_t)16*M1;
    __half* w2_16  = s16 + (size_t)20*M1;
    __half* bq16   = s16 + (size_t)24*M1;
    __half* bk16   = s16 + (size_t)28*M1;
    __half* bv16   = s16 + (size_t)32*M1;
    __half* batt16 = s16 + (size_t)36*M1;
    __half* bx1_16 = s16 + (size_t)40*M1;
    __half* bx2_16 = s16 + (size_t)44*M1;
    __half* bff16  = s16 + (size_t)48*M1;
    __half* bk2    = s16 + (size_t)64*M1;   // cross K
    __half* bv2    = s16 + (size_t)68*M1;   // cross V

    CvtArgs ca;
    ca.job[0]  = { x,   x16,   4*M1 };
    ca.job[1]  = { mem, mem16, 4*M1 };
    ca.job[2]  = { swq, wq16,  M1 };
    ca.job[3]  = { swk, wk16,  M1 };
    ca.job[4]  = { swv, wv16,  M1 };
    ca.job[5]  = { swo, wo16,  M1 };
    ca.job[6]  = { cwq, cq16,  M1 };
    ca.job[7]  = { cwk, ck16,  M1 };
    ca.job[8]  = { cwv, cv16,  M1 };
    ca.job[9]  = { cwo, co16,  M1 };
    ca.job[10] = { w1,  w1_16, 4*M1 };
    ca.job[11] = { w2,  w2_16, 4*M1 };
    dim3 gCvt(512, 12);
    cvt_kernel<<<gCvt, 256>>>(ca);

    dim3 gP(Dd / 128, RB / 128);
    dim3 gP5(Dd / 128, RB / 128, 5);
    dim3 gF1(FFf / 128, RB / 128);
    dim3 gAttn(Ll / 64, Bb * Hh);

    // ---- fused projections: self Q/K/V + cross K/V in ONE launch ----
    Gemm5Args g5;
    g5.job[0] = { x16,   wq16, sbq, bq16 };
    g5.job[1] = { x16,   wk16, sbk, bk16 };
    g5.job[2] = { x16,   wv16, sbv, bv16 };
    g5.job[3] = { mem16, ck16, cbk, bk2  };
    g5.job[4] = { mem16, cv16, cbv, bv2  };
    hgemm16_b5_kernel<<<gP5, 256>>>(g5);

    // ---- self-attention ----
    attn_mma_kernel<true><<<gAttn, 128>>>(bq16, bk16, bv16, batt16, Ll);
    hgemm16_kernel<false><<<gP, 256>>>(batt16, wo16, sbo, btmp, nullptr, Dd, Dd);
    add_ln_kernel<<<RB, 256>>>(x, btmp, g1, be1, bx1, bx1_16);

    // ---- cross-attention ----
    hgemm16_kernel<false><<<gP, 256>>>(bx1_16, cq16, cbq, nullptr, bq16, Dd, Dd);
    attn_mma_kernel<false><<<gAttn, 128>>>(bq16, bk2, bv2, batt16, Mm);
    hgemm16_kernel<false><<<gP, 256>>>(batt16, co16, cbo, btmp, nullptr, Dd, Dd);
    add_ln_kernel<<<RB, 256>>>(bx1, btmp, g2, be2, bx2, bx2_16);

    // ---- FFN ----
    hgemm16_kernel<true><<<gF1, 256>>>(bx2_16, w1_16, b1, nullptr, bff16, Dd, FFf);
    hgemm16_kernel<false><<<gP, 256>>>(bff16, w2_16, b2, btmp, nullptr, FFf, Dd);
    add_ln_kernel<<<RB, 256>>>(bx2, btmp, g3, be3, (float*)d_out, nullptr);
}